// round 2
// baseline (speedup 1.0000x reference)
#include <cuda_runtime.h>
#include <math.h>

// Problem constants
#define BB 4
#define NN 2048
#define DD 1024
#define HH 16
#define HD 64
#define MTOT (BB*NN)          // 8192
#define ATT_SCALE 0.125f      // 64^-0.5

// ---------------- scratch (static device memory; no allocations) ------------
__device__ float d_cpc[4 * 64 * 64];          // 4 x (r1 x r2)
__device__ float d_T[4 * 64 * 1024];          // 4 x (r x D)   T = cp @ V
__device__ float d_Weff[4 * 1024 * 1024];     // folded weights q,k,v,proj
__device__ float d_q[MTOT * DD];
__device__ float d_k[MTOT * DD];
__device__ float d_v[MTOT * DD];
__device__ float d_x[MTOT * DD];              // attention output

// ---------------- prep kernels ----------------------------------------------
// CPc[x][y][f] = sum_r CP_C[x][y][r] * CP_att[r][f]   -> stored as d_cpc[f][x][y]
__global__ void cpc_kernel(const float* __restrict__ cpC,
                           const float* __restrict__ cpAtt) {
    int idx = blockIdx.x * 256 + threadIdx.x;       // 16384 total
    int f = idx >> 12;
    int rem = idx & 4095;                           // x*64+y
    const float* c = cpC + rem * 64;
    float s = 0.f;
#pragma unroll 8
    for (int r = 0; r < 64; r++) s += c[r] * cpAtt[r * 4 + f];
    d_cpc[f * 4096 + rem] = s;
}

// T[f][x][d] = sum_y cp_f[x][y] * V[y][d]
__global__ void tmat_kernel(const float* __restrict__ Vw) {
    int idx = blockIdx.x * 256 + threadIdx.x;       // 262144 total
    int f = idx >> 16;
    int rem = idx & 65535;
    int x = rem >> 10;
    int d = rem & 1023;
    const float* cp = d_cpc + f * 4096 + x * 64;
    float s = 0.f;
#pragma unroll 8
    for (int y = 0; y < 64; y++) s += cp[y] * Vw[y * 1024 + d];
    d_T[idx] = s;
}

// Weff[f][i][d] = W_f[i][d] + sum_x U[i][x] * T[f][x][d]
__global__ void weff_kernel(const float* __restrict__ Wq, const float* __restrict__ Wk,
                            const float* __restrict__ Wv, const float* __restrict__ Wp,
                            const float* __restrict__ U) {
    int idx = blockIdx.x * 256 + threadIdx.x;       // 4 * 1M total
    int f = idx >> 20;
    int rem = idx & 1048575;
    int i = rem >> 10;
    int d = rem & 1023;
    const float* W = (f == 0) ? Wq : (f == 1) ? Wk : (f == 2) ? Wv : Wp;
    const float* Tf = d_T + f * 65536;
    const float* Ur = U + i * 64;
    float s = W[rem];
#pragma unroll 8
    for (int x = 0; x < 64; x++) s += Ur[x] * Tf[x * 1024 + d];
    d_Weff[idx] = s;
}

// ---------------- SGEMM (batched over z): C[M x 1024] = A @ B (+bias) --------
// 128x128x8 tile, 256 threads, 8x8 microtile, DOUBLE-BUFFERED smem.
// blockIdx.z selects (A, B-slice, C) so QKV runs as ONE launch (wave packing).
__global__ void __launch_bounds__(256, 2)
sgemm3_kernel(const float* __restrict__ A0, const float* __restrict__ A1,
              const float* __restrict__ A2,
              const float* __restrict__ Bw, const float* __restrict__ bias,
              float* __restrict__ C0, float* __restrict__ C1, float* __restrict__ C2) {
    const int K = 1024, Nn = 1024;
    __shared__ float As[2][8][132];   // transposed, padded
    __shared__ float Bs[2][8][128];

    int z = blockIdx.z;
    const float* A  = (z == 0) ? A0 : (z == 1) ? A1 : A2;
    float*       C  = (z == 0) ? C0 : (z == 1) ? C1 : C2;
    const float* Bm = Bw + (long)z * 1048576;

    int bx = blockIdx.x * 128;
    int by = blockIdx.y * 128;
    int tid = threadIdx.x;
    int tx = tid & 15;
    int ty = tid >> 4;

    int arow = tid >> 1;           // 0..127
    int acol = (tid & 1) * 4;      // 0 or 4
    int brow = tid >> 5;           // 0..7
    int bcol = (tid & 31) * 4;     // 0..124

    const float* Aptr = A + (long)(by + arow) * K + acol;
    const float* Bptr = Bm + (long)brow * Nn + bx + bcol;

    float acc[8][8];
#pragma unroll
    for (int i = 0; i < 8; i++)
#pragma unroll
        for (int j = 0; j < 8; j++) acc[i][j] = 0.f;

    // prologue: load slab 0 into buffer 0
    float4 aReg = *(const float4*)Aptr;
    float4 bReg = *(const float4*)Bptr;
    As[0][acol + 0][arow] = aReg.x;
    As[0][acol + 1][arow] = aReg.y;
    As[0][acol + 2][arow] = aReg.z;
    As[0][acol + 3][arow] = aReg.w;
    *(float4*)&Bs[0][brow][bcol] = bReg;
    __syncthreads();

    int cur = 0;
    for (int kt = 0; kt < K / 8; kt++) {
        // prefetch next slab from gmem into registers (overlaps compute)
        if (kt + 1 < K / 8) {
            aReg = *(const float4*)(Aptr + (kt + 1) * 8);
            bReg = *(const float4*)(Bptr + (long)(kt + 1) * 8 * Nn);
        }

#pragma unroll
        for (int kk = 0; kk < 8; kk++) {
            float a0[4], a1[4], b0[4], b1[4];
            *(float4*)a0 = *(const float4*)&As[cur][kk][ty * 4];
            *(float4*)a1 = *(const float4*)&As[cur][kk][64 + ty * 4];
            *(float4*)b0 = *(const float4*)&Bs[cur][kk][tx * 4];
            *(float4*)b1 = *(const float4*)&Bs[cur][kk][64 + tx * 4];
#pragma unroll
            for (int i = 0; i < 4; i++)
#pragma unroll
                for (int j = 0; j < 4; j++) {
                    acc[i][j]         += a0[i] * b0[j];
                    acc[i][j + 4]     += a0[i] * b1[j];
                    acc[i + 4][j]     += a1[i] * b0[j];
                    acc[i + 4][j + 4] += a1[i] * b1[j];
                }
        }

        // store next slab into the other buffer; single sync per slab
        if (kt + 1 < K / 8) {
            int nxt = cur ^ 1;
            As[nxt][acol + 0][arow] = aReg.x;
            As[nxt][acol + 1][arow] = aReg.y;
            As[nxt][acol + 2][arow] = aReg.z;
            As[nxt][acol + 3][arow] = aReg.w;
            *(float4*)&Bs[nxt][brow][bcol] = bReg;
            __syncthreads();
            cur = nxt;
        }
    }

    // epilogue
#pragma unroll
    for (int hi = 0; hi < 2; hi++) {
#pragma unroll
        for (int i = 0; i < 4; i++) {
            int row = by + hi * 64 + ty * 4 + i;
            float* Crow = C + (long)row * Nn + bx;
#pragma unroll
            for (int hj = 0; hj < 2; hj++) {
                int col = hj * 64 + tx * 4;
                float4 r;
                r.x = acc[hi * 4 + i][hj * 4 + 0];
                r.y = acc[hi * 4 + i][hj * 4 + 1];
                r.z = acc[hi * 4 + i][hj * 4 + 2];
                r.w = acc[hi * 4 + i][hj * 4 + 3];
                if (bias) {
                    float4 bb = *(const float4*)(bias + bx + col);
                    r.x += bb.x; r.y += bb.y; r.z += bb.z; r.w += bb.w;
                }
                *(float4*)(Crow + col) = r;
            }
        }
    }
}

// ---------------- flash attention --------------------------------------------
// grid: (32 q-tiles, 16 heads, 4 batch); 256 threads; 64-query tile; hd = 64
__global__ void __launch_bounds__(256, 2)
attn_kernel(const float* __restrict__ q, const float* __restrict__ k,
            const float* __restrict__ v, float* __restrict__ o) {
    __shared__ float Qs[64][64];   // transposed [d][i], pre-scaled
    __shared__ float KP[64][64];   // K transposed [d][j]; reused as P [i][j]
    __shared__ float Vs[64][64];   // natural [j][d]

    int b = blockIdx.z, h = blockIdx.y, qt = blockIdx.x;
    int tid = threadIdx.x;
    int tx = tid & 15, ty = tid >> 4;

    const long hoff = (long)h * HD;
    const float* qbase = q + ((long)(b * NN + qt * 64)) * DD + hoff;
    const float* kbase = k + ((long)b * NN) * DD + hoff;
    const float* vbase = v + ((long)b * NN) * DD + hoff;

    // load Q tile transposed, fold in ATT_SCALE
#pragma unroll
    for (int it = 0; it < 4; it++) {
        int fid = tid + 256 * it;
        int i = fid >> 4, d4 = (fid & 15) << 2;
        float4 val = *(const float4*)(qbase + (long)i * DD + d4);
        Qs[d4 + 0][i] = val.x * ATT_SCALE;
        Qs[d4 + 1][i] = val.y * ATT_SCALE;
        Qs[d4 + 2][i] = val.z * ATT_SCALE;
        Qs[d4 + 3][i] = val.w * ATT_SCALE;
    }

    float m_r[4], l_r[4], Oc[4][4];
#pragma unroll
    for (int i = 0; i < 4; i++) {
        m_r[i] = -1e30f; l_r[i] = 0.f;
#pragma unroll
        for (int j = 0; j < 4; j++) Oc[i][j] = 0.f;
    }

    for (int kt = 0; kt < 32; kt++) {
        __syncthreads();   // also makes Q tile visible on first iteration
        const float* kb = kbase + (long)kt * 64 * DD;
        const float* vb = vbase + (long)kt * 64 * DD;
#pragma unroll
        for (int it = 0; it < 4; it++) {
            int fid = tid + 256 * it;
            int i = fid >> 4, d4 = (fid & 15) << 2;
            float4 kv = *(const float4*)(kb + (long)i * DD + d4);
            KP[d4 + 0][i] = kv.x; KP[d4 + 1][i] = kv.y;
            KP[d4 + 2][i] = kv.z; KP[d4 + 3][i] = kv.w;
            float4 vv = *(const float4*)(vb + (long)i * DD + d4);
            *(float4*)&Vs[i][d4] = vv;
        }
        __syncthreads();

        // S = (Q*scale) K^T : 4x4 microtile, outer product over d
        float s[4][4];
#pragma unroll
        for (int i = 0; i < 4; i++)
#pragma unroll
            for (int j = 0; j < 4; j++) s[i][j] = 0.f;

        for (int d = 0; d < 64; d++) {
            float aq[4], bk[4];
#pragma unroll
            for (int i = 0; i < 4; i++) aq[i] = Qs[d][ty * 4 + i];
#pragma unroll
            for (int j = 0; j < 4; j++) bk[j] = KP[d][tx * 4 + j];
#pragma unroll
            for (int i = 0; i < 4; i++)
#pragma unroll
                for (int j = 0; j < 4; j++) s[i][j] += aq[i] * bk[j];
        }

        // online softmax: row stats across the 16 tx lanes (shfl within half-warp)
        float mnew[4], corr[4], rsum[4];
#pragma unroll
        for (int i = 0; i < 4; i++) {
            float rmax = fmaxf(fmaxf(s[i][0], s[i][1]), fmaxf(s[i][2], s[i][3]));
#pragma unroll
            for (int off = 8; off >= 1; off >>= 1)
                rmax = fmaxf(rmax, __shfl_xor_sync(0xffffffffu, rmax, off));
            mnew[i] = fmaxf(m_r[i], rmax);
            corr[i] = __expf(m_r[i] - mnew[i]);
            m_r[i] = mnew[i];
            float rs = 0.f;
#pragma unroll
            for (int j = 0; j < 4; j++) {
                float p = __expf(s[i][j] - mnew[i]);
                s[i][j] = p;
                rs += p;
            }
#pragma unroll
            for (int off = 8; off >= 1; off >>= 1)
                rs += __shfl_xor_sync(0xffffffffu, rs, off);
            rsum[i] = rs;
            l_r[i] = l_r[i] * corr[i] + rsum[i];
#pragma unroll
            for (int j = 0; j < 4; j++) Oc[i][j] *= corr[i];
        }

        __syncthreads();   // done reading KP as K
        // store P into KP as [i][j]
#pragma unroll
        for (int i = 0; i < 4; i++) {
            int row = ty * 4 + i;
            KP[row][tx * 4 + 0] = s[i][0];
            KP[row][tx * 4 + 1] = s[i][1];
            KP[row][tx * 4 + 2] = s[i][2];
            KP[row][tx * 4 + 3] = s[i][3];
        }
        __syncthreads();

        // O += P V : 4x4 microtile, outer product over j
        for (int j = 0; j < 64; j++) {
            float ap[4], bv[4];
#pragma unroll
            for (int i = 0; i < 4; i++) ap[i] = KP[ty * 4 + i][j];
            *(float4*)bv = *(const float4*)&Vs[j][tx * 4];
#pragma unroll
            for (int i = 0; i < 4; i++)
#pragma unroll
                for (int jj = 0; jj < 4; jj++) Oc[i][jj] += ap[i] * bv[jj];
        }
    }

    // write O / l  ->  x in (B, N, H*hd) layout
#pragma unroll
    for (int i = 0; i < 4; i++) {
        int row = qt * 64 + ty * 4 + i;
        float inv = 1.f / l_r[i];
        float4 r;
        r.x = Oc[i][0] * inv; r.y = Oc[i][1] * inv;
        r.z = Oc[i][2] * inv; r.w = Oc[i][3] * inv;
        *(float4*)(o + ((long)(b * NN + row)) * DD + hoff + tx * 4) = r;
    }
}

// ---------------- launch ------------------------------------------------------
extern "C" void kernel_launch(void* const* d_in, const int* in_sizes, int n_in,
                              void* d_out, int out_size) {
    const float* in_q   = (const float*)d_in[0];
    const float* in_k   = (const float*)d_in[1];
    const float* in_v   = (const float*)d_in[2];
    const float* Wq     = (const float*)d_in[3];
    const float* Wk     = (const float*)d_in[4];
    const float* Wv     = (const float*)d_in[5];
    const float* Wproj  = (const float*)d_in[6];
    const float* bproj  = (const float*)d_in[7];
    const float* cpAtt  = (const float*)d_in[8];
    const float* cpC    = (const float*)d_in[9];
    const float* Uw     = (const float*)d_in[10];
    const float* Vw     = (const float*)d_in[11];
    float* out = (float*)d_out;

    float *dq, *dk, *dv, *dx, *dweff;
    cudaGetSymbolAddress((void**)&dq, d_q);
    cudaGetSymbolAddress((void**)&dk, d_k);
    cudaGetSymbolAddress((void**)&dv, d_v);
    cudaGetSymbolAddress((void**)&dx, d_x);
    cudaGetSymbolAddress((void**)&dweff, d_Weff);

    // fold CP adapter into effective weights
    cpc_kernel<<<64, 256>>>(cpC, cpAtt);
    tmat_kernel<<<1024, 256>>>(Vw);
    weff_kernel<<<16384, 256>>>(Wq, Wk, Wv, Wproj, Uw);

    // q / k / v projections fused into ONE launch: z selects (A, B, C)
    dim3 ggrid3(1024 / 128, MTOT / 128, 3);
    sgemm3_kernel<<<ggrid3, 256>>>(in_q, in_k, in_v, dweff, nullptr, dq, dk, dv);

    // attention
    dim3 agrid(NN / 64, HH, BB);
    attn_kernel<<<agrid, 256>>>(dq, dk, dv, dx);

    // output projection (+bias), with folded p_cp adapter (weights slot 3)
    dim3 pgrid(1024 / 128, MTOT / 128, 1);
    sgemm3_kernel<<<pgrid, 256>>>(dx, dx, dx, dweff + 3 * 1048576, bproj, out, out, out);
}